// round 6
// baseline (speedup 1.0000x reference)
#include <cuda_runtime.h>
#include <cstdint>

// IDWT_2D: x [B=4, 4*C=256, H=256, W=256] f32, filters [4,2,2] f32
// s[b,g,h,w] = sum_n x[b, n*64+g, h, w]
// y[b, g*4+j, 2h+a, 2w+c] = s[b,g,h,w] * f[j,a,c]
// Output: [4, 256, 512, 512] f32

static constexpr int C = 64;
static constexpr int H = 256;
static constexpr int W = 256;
static constexpr int SUBBAND_STRIDE = C * H * W;
static constexpr int OUT_W = 2 * W;                   // 512
static constexpr int OUT_CH_STRIDE = (2 * H) * OUT_W; // 512*512

static constexpr unsigned TOTAL_SEGS = 131072;  // B*C*H*2 half-rows
static constexpr unsigned GRID_WARPS = 16384;   // persistent warps
static constexpr int ITERS = TOTAL_SEGS / GRID_WARPS;  // 8

// half-row input address for (seg, lane)
__device__ __forceinline__ const float* in_addr(const float* __restrict__ x,
                                                unsigned seg, int lane) {
    int half = seg & 1;
    int h    = (seg >> 1) & (H - 1);
    int g    = (seg >> 9) & (C - 1);
    int b    = seg >> 15;
    return x + (((size_t)(b * 4 * C + g) * H + h) * W) + half * 128 + 2 * lane;
}

__device__ __forceinline__ void load8(const float* __restrict__ xb,
                                      float2 v0[4], float2 v1[4]) {
    #pragma unroll
    for (int n = 0; n < 4; ++n) {
        v0[n] = *reinterpret_cast<const float2*>(xb + n * SUBBAND_STRIDE);
        v1[n] = *reinterpret_cast<const float2*>(xb + n * SUBBAND_STRIDE + 64);
    }
}

// Persistent warps, software-pipelined: next iteration's loads are issued
// BEFORE the current iteration's stores, keeping reads in flight during the
// write burst (smoother R/W mix at the DRAM controller).
__global__ __launch_bounds__(256, 6) void idwt2d_kernel(
    const float* __restrict__ x,
    const float* __restrict__ filters,
    float* __restrict__ out)
{
    unsigned warpId = blockIdx.x * 8u + (threadIdx.x >> 5);
    int lane = threadIdx.x & 31;

    const float4* f4 = reinterpret_cast<const float4*>(filters);

    unsigned seg = warpId;
    float2 v0[4], v1[4];
    load8(in_addr(x, seg, lane), v0, v1);

    #pragma unroll
    for (int it = 0; it < ITERS; ++it) {
        // ---- prefetch next segment's loads (independent of current work) ----
        unsigned nseg = seg + GRID_WARPS;
        float2 w0[4], w1[4];
        if (it < ITERS - 1)
            load8(in_addr(x, nseg, lane), w0, w1);

        // ---- sum current segment's 4 sub-bands ----
        float2 s0, s1;
        s0.x = (v0[0].x + v0[1].x) + (v0[2].x + v0[3].x);
        s0.y = (v0[0].y + v0[1].y) + (v0[2].y + v0[3].y);
        s1.x = (v1[0].x + v1[1].x) + (v1[2].x + v1[3].x);
        s1.y = (v1[0].y + v1[1].y) + (v1[2].y + v1[3].y);

        // ---- store 16 lane-contiguous 512B blocks ----
        {
            int half = seg & 1;
            int h    = (seg >> 1) & (H - 1);
            int g    = (seg >> 9) & (C - 1);
            int b    = seg >> 15;
            float* obase = out
                + ((size_t)(b * 4 * C + g * 4) * (2 * H) + 2 * h) * OUT_W
                + half * 256 + 4 * lane;

            #pragma unroll
            for (int j = 0; j < 4; ++j) {
                float4 F = __ldg(f4 + j);
                float* orow = obase + (size_t)j * OUT_CH_STRIDE;
                float4 v;
                v.x = s0.x * F.x; v.y = s0.x * F.y; v.z = s0.y * F.x; v.w = s0.y * F.y;
                reinterpret_cast<float4*>(orow)[0] = v;
                v.x = s1.x * F.x; v.y = s1.x * F.y; v.z = s1.y * F.x; v.w = s1.y * F.y;
                reinterpret_cast<float4*>(orow + 128)[0] = v;
                v.x = s0.x * F.z; v.y = s0.x * F.w; v.z = s0.y * F.z; v.w = s0.y * F.w;
                reinterpret_cast<float4*>(orow + OUT_W)[0] = v;
                v.x = s1.x * F.z; v.y = s1.x * F.w; v.z = s1.y * F.z; v.w = s1.y * F.w;
                reinterpret_cast<float4*>(orow + OUT_W + 128)[0] = v;
            }
        }

        // ---- rotate pipeline ----
        if (it < ITERS - 1) {
            #pragma unroll
            for (int n = 0; n < 4; ++n) { v0[n] = w0[n]; v1[n] = w1[n]; }
            seg = nseg;
        }
    }
}

extern "C" void kernel_launch(void* const* d_in, const int* in_sizes, int n_in,
                              void* d_out, int out_size) {
    const float* x       = (const float*)d_in[0];
    const float* filters = (const float*)d_in[1];
    float* out           = (float*)d_out;

    // 16384 persistent warps = 2048 blocks x 8 warps, 8 iterations each
    idwt2d_kernel<<<2048, 256>>>(x, filters, out);
}

// round 7
// speedup vs baseline: 1.0694x; 1.0694x over previous
#include <cuda_runtime.h>
#include <cstdint>

// IDWT_2D: x [B=4, 4*C=256, H=256, W=256] f32, filters [4,2,2] f32
// s[b,g,h,w] = sum_n x[b, n*64+g, h, w]
// y[b, g*4+j, 2h+a, 2w+c] = s[b,g,h,w] * f[j,a,c]
// Output: [4, 256, 512, 512] f32

static constexpr int C = 64;                 // groups
static constexpr int H = 256;
static constexpr int W = 256;
static constexpr int SUBBAND_STRIDE = C * H * W;      // offset between sub-bands n
static constexpr int OUT_W = 2 * W;                   // 512
static constexpr int OUT_CH_STRIDE = (2 * H) * OUT_W; // 512*512

// One warp handles one (b, g, h, half) = 128 consecutive input pixels.
// Thread k holds input pixels {2k, 2k+1} (s0) and {64+2k, 64+2k+1} (s1).
// Every STG.128 across the warp is a contiguous 512B full-sector block.
// 128-thread blocks, 16 blocks/SM: same 64-warp/SM ceiling as R5 but finer
// CTA allocation granularity -> higher achieved occupancy, smoother waves.
__global__ __launch_bounds__(128, 16) void idwt2d_kernel(
    const float* __restrict__ x,
    const float* __restrict__ filters,
    float* __restrict__ out)
{
    unsigned seg = blockIdx.x * 4u + (threadIdx.x >> 5);  // global warp id
    int lane = threadIdx.x & 31;
    int half = seg & 1;                 // which half of the input row
    int h    = (seg >> 1) & (H - 1);
    int g    = (seg >> 9) & (C - 1);
    int b    = seg >> 15;

    // input row base for sub-band 0, this warp's half-row, this lane
    const float* xb = x + (((size_t)(b * 4 * C + g) * H + h) * W)
                        + half * 128 + 2 * lane;

    // gather + sum the 4 sub-bands (coalesced float2 loads: 8B/lane)
    float2 s0 = *reinterpret_cast<const float2*>(xb);
    float2 s1 = *reinterpret_cast<const float2*>(xb + 64);
    #pragma unroll
    for (int n = 1; n < 4; ++n) {
        float2 t0 = *reinterpret_cast<const float2*>(xb + n * SUBBAND_STRIDE);
        float2 t1 = *reinterpret_cast<const float2*>(xb + n * SUBBAND_STRIDE + 64);
        s0.x += t0.x; s0.y += t0.y;
        s1.x += t1.x; s1.y += t1.y;
    }

    // filters: [4,2,2] -> one float4 per j: {a0c0, a0c1, a1c0, a1c1}
    const float4* f4 = reinterpret_cast<const float4*>(filters);

    // output base: channel g*4, row 2h, column 256*half + 4*lane
    float* obase = out + ((size_t)(b * 4 * C + g * 4) * (2 * H) + 2 * h) * OUT_W
                       + half * 256 + 4 * lane;

    #pragma unroll
    for (int j = 0; j < 4; ++j) {
        float4 F = __ldg(f4 + j);
        float* orow = obase + (size_t)j * OUT_CH_STRIDE;

        float4 v;
        // a = 0, first 512B block (from s0: pixels 2k, 2k+1)
        v.x = s0.x * F.x; v.y = s0.x * F.y; v.z = s0.y * F.x; v.w = s0.y * F.y;
        reinterpret_cast<float4*>(orow)[0] = v;
        // a = 0, second 512B block (from s1: pixels 64+2k, 64+2k+1)
        v.x = s1.x * F.x; v.y = s1.x * F.y; v.z = s1.y * F.x; v.w = s1.y * F.y;
        reinterpret_cast<float4*>(orow + 128)[0] = v;
        // a = 1 row
        v.x = s0.x * F.z; v.y = s0.x * F.w; v.z = s0.y * F.z; v.w = s0.y * F.w;
        reinterpret_cast<float4*>(orow + OUT_W)[0] = v;
        v.x = s1.x * F.z; v.y = s1.x * F.w; v.z = s1.y * F.z; v.w = s1.y * F.w;
        reinterpret_cast<float4*>(orow + OUT_W + 128)[0] = v;
    }
}

extern "C" void kernel_launch(void* const* d_in, const int* in_sizes, int n_in,
                              void* d_out, int out_size) {
    const float* x       = (const float*)d_in[0];
    const float* filters = (const float*)d_in[1];
    float* out           = (float*)d_out;

    // total warps = B*C*H*2 = 131072 ; 4 warps/block -> 32768 blocks
    idwt2d_kernel<<<32768, 128>>>(x, filters, out);
}